// round 6
// baseline (speedup 1.0000x reference)
#include <cuda_runtime.h>

// KAN layer forward, fused. out[b,o] = sum_i [ spline window dot + silu term ].
// Coefficient tile layout: cpad[i][slot][o] with o innermost (8 floats =
// 2 x float4), per-i stride 124 words (124/4=31 odd => lane->float4-group
// map is a permutation: every LDS.128 is conflict-free). A lane owns edges
// i=lane, lane+32; one slot read = 2 x LDS.128 covering all 8 outputs.
// Slots 0..13: zero-padded mask*scale_sp*coef window; slot 14: mask*scale_base.

#define IN_DIM  64
#define OUT_DIM 64
#define NW      8            // warps per block
#define RROWS   16           // batch rows per block (2 per warp)
#define OT      8            // outputs per block
#define ISTRIDE 124          // words per i row: 15 slots * 8 + 4 pad (31 odd)
#define THREADS (NW * 32)

__global__ __launch_bounds__(THREADS, 4)
void kan_fused(const float* __restrict__ inp,
               const float* __restrict__ gridp,
               const float* __restrict__ coefp,
               const float* __restrict__ sbase,
               const float* __restrict__ ssp,
               const float* __restrict__ maskp,
               float* __restrict__ out,
               int batch)
{
    __shared__ __align__(16) float cpad[IN_DIM * ISTRIDE];   // 31.0 KB

    const int tid   = threadIdx.x;
    const int otile = blockIdx.x * OT;

    // ---- prologue: cpad[i*124 + slot*8 + oo] ----
    //   slot 0..13 : (slot-3 in [0,8)) ? mask*ssp*coef[s][slot-3] : 0
    //   slot 14    : mask*sbase
    // edge s = (otile+oo)*64 + i
    for (int idx = tid; idx < IN_DIM * 15 * OT; idx += THREADS) {
        const int oo   = idx & (OT - 1);
        const int rem  = idx >> 3;
        const int slot = rem % 15;
        const int i    = rem / 15;
        const int s    = (otile + oo) * IN_DIM + i;
        float v;
        if (slot == 14) {
            v = maskp[s] * sbase[s];
        } else {
            const int j = slot - 3;
            v = (j >= 0 && j < 8) ? maskp[s] * ssp[s] * __ldg(coefp + s * 8 + j)
                                  : 0.0f;
        }
        cpad[i * ISTRIDE + slot * 8 + oo] = v;
    }

    const int lane = tid & 31;
    const int wrp  = tid >> 5;
    const int i0 = lane, i1 = lane + 32;

    // row-invariant knot params per edge
    float t0[2], invh[2];
    #pragma unroll
    for (int e = 0; e < 2; ++e) {
        const int i = lane + 32 * e;
        const float g0 = __ldg(gridp + i * 6 + 0);
        const float g5 = __ldg(gridp + i * 6 + 5);
        const float h  = (g5 - g0) * 0.2f;
        t0[e]   = g0 - 3.0f * h;
        invh[e] = 1.0f / h;
    }

    const float* cp0 = &cpad[i0 * ISTRIDE];
    const float* cp1 = &cpad[i1 * ISTRIDE];

    __syncthreads();

    #pragma unroll 1
    for (int it = 0; it < RROWS / NW; ++it) {
        const int b = blockIdx.y * RROWS + it * NW + wrp;   // warp-uniform
        if (b >= batch) continue;

        const float x0 = inp[b * IN_DIM + i0];
        const float x1 = inp[b * IN_DIM + i1];

        float wa[4], wb[4];
        int mi0, mi1;
        {
            const float mf = (x0 - t0[0]) * invh[0];
            int mi = (int)floorf(mf);
            const float ok = (mi >= 0 && mi < 11) ? 1.0f : 0.0f;
            mi = max(0, min(10, mi));
            const float u = mf - (float)mi, v = 1.0f - u;
            const float u2 = u * u, u3 = u2 * u;
            wa[0] = ok * (v * v * v * (1.0f / 6.0f));
            wa[3] = ok * (u3 * (1.0f / 6.0f));
            wa[1] = ok * ((2.0f / 3.0f) - u2 + 0.5f * u3);
            wa[2] = ok - wa[0] - wa[1] - wa[3];
            mi0 = mi;
        }
        {
            const float mf = (x1 - t0[1]) * invh[1];
            int mi = (int)floorf(mf);
            const float ok = (mi >= 0 && mi < 11) ? 1.0f : 0.0f;
            mi = max(0, min(10, mi));
            const float u = mf - (float)mi, v = 1.0f - u;
            const float u2 = u * u, u3 = u2 * u;
            wb[0] = ok * (v * v * v * (1.0f / 6.0f));
            wb[3] = ok * (u3 * (1.0f / 6.0f));
            wb[1] = ok * ((2.0f / 3.0f) - u2 + 0.5f * u3);
            wb[2] = ok - wb[0] - wb[1] - wb[3];
            mi1 = mi;
        }
        const float s0 = __fdividef(x0, 1.0f + __expf(-x0));
        const float s1 = __fdividef(x1, 1.0f + __expf(-x1));

        float acc[OT];
        #pragma unroll
        for (int k = 0; k < OT; ++k) acc[k] = 0.0f;

        // edge 0: 4 window slots + silu slot, each 2 x LDS.128 over o
        #pragma unroll
        for (int r = 0; r < 4; ++r) {
            const float4 cA = *(const float4*)(cp0 + (mi0 + r) * 8);
            const float4 cB = *(const float4*)(cp0 + (mi0 + r) * 8 + 4);
            const float w = wa[r];
            acc[0] = fmaf(cA.x, w, acc[0]); acc[1] = fmaf(cA.y, w, acc[1]);
            acc[2] = fmaf(cA.z, w, acc[2]); acc[3] = fmaf(cA.w, w, acc[3]);
            acc[4] = fmaf(cB.x, w, acc[4]); acc[5] = fmaf(cB.y, w, acc[5]);
            acc[6] = fmaf(cB.z, w, acc[6]); acc[7] = fmaf(cB.w, w, acc[7]);
        }
        {
            const float4 cA = *(const float4*)(cp0 + 14 * 8);
            const float4 cB = *(const float4*)(cp0 + 14 * 8 + 4);
            acc[0] = fmaf(cA.x, s0, acc[0]); acc[1] = fmaf(cA.y, s0, acc[1]);
            acc[2] = fmaf(cA.z, s0, acc[2]); acc[3] = fmaf(cA.w, s0, acc[3]);
            acc[4] = fmaf(cB.x, s0, acc[4]); acc[5] = fmaf(cB.y, s0, acc[5]);
            acc[6] = fmaf(cB.z, s0, acc[6]); acc[7] = fmaf(cB.w, s0, acc[7]);
        }
        // edge 1
        #pragma unroll
        for (int r = 0; r < 4; ++r) {
            const float4 cA = *(const float4*)(cp1 + (mi1 + r) * 8);
            const float4 cB = *(const float4*)(cp1 + (mi1 + r) * 8 + 4);
            const float w = wb[r];
            acc[0] = fmaf(cA.x, w, acc[0]); acc[1] = fmaf(cA.y, w, acc[1]);
            acc[2] = fmaf(cA.z, w, acc[2]); acc[3] = fmaf(cA.w, w, acc[3]);
            acc[4] = fmaf(cB.x, w, acc[4]); acc[5] = fmaf(cB.y, w, acc[5]);
            acc[6] = fmaf(cB.z, w, acc[6]); acc[7] = fmaf(cB.w, w, acc[7]);
        }
        {
            const float4 cA = *(const float4*)(cp1 + 14 * 8);
            const float4 cB = *(const float4*)(cp1 + 14 * 8 + 4);
            acc[0] = fmaf(cA.x, s1, acc[0]); acc[1] = fmaf(cA.y, s1, acc[1]);
            acc[2] = fmaf(cA.z, s1, acc[2]); acc[3] = fmaf(cA.w, s1, acc[3]);
            acc[4] = fmaf(cB.x, s1, acc[4]); acc[5] = fmaf(cB.y, s1, acc[5]);
            acc[6] = fmaf(cB.z, s1, acc[6]); acc[7] = fmaf(cB.w, s1, acc[7]);
        }

        // fold-by-halves butterfly: 8 accs x 32 lanes -> 8 sums in 9 shfl
        #pragma unroll
        for (int k = 0; k < 4; ++k) {
            float send = (lane & 16) ? acc[k] : acc[k + 4];
            float got  = __shfl_xor_sync(0xffffffffu, send, 16);
            acc[k] = ((lane & 16) ? acc[k + 4] : acc[k]) + got;
        }
        #pragma unroll
        for (int k = 0; k < 2; ++k) {
            float send = (lane & 8) ? acc[k] : acc[k + 2];
            float got  = __shfl_xor_sync(0xffffffffu, send, 8);
            acc[k] = ((lane & 8) ? acc[k + 2] : acc[k]) + got;
        }
        {
            float send = (lane & 4) ? acc[0] : acc[1];
            float got  = __shfl_xor_sync(0xffffffffu, send, 4);
            acc[0] = ((lane & 4) ? acc[1] : acc[0]) + got;
        }
        acc[0] += __shfl_xor_sync(0xffffffffu, acc[0], 2);
        acc[0] += __shfl_xor_sync(0xffffffffu, acc[0], 1);

        if ((lane & 3) == 0) {
            const int ol = ((lane >> 4) & 1) * 4 + ((lane >> 3) & 1) * 2
                         + ((lane >> 2) & 1);
            out[b * OUT_DIM + otile + ol] = acc[0];
        }
    }
}

extern "C" void kernel_launch(void* const* d_in, const int* in_sizes, int n_in,
                              void* d_out, int out_size)
{
    const float* inp   = (const float*)d_in[0];   // (batch, 64)
    const float* gridp = (const float*)d_in[1];   // (4096, 6)
    const float* coefp = (const float*)d_in[2];   // (4096, 8)
    const float* sbase = (const float*)d_in[3];   // (4096,)
    const float* ssp   = (const float*)d_in[4];   // (4096,)
    const float* maskp = (const float*)d_in[5];   // (4096,)
    float* out = (float*)d_out;                   // (batch, 64)

    const int batch = in_sizes[0] / IN_DIM;

    dim3 grid(OUT_DIM / OT, (batch + RROWS - 1) / RROWS);   // 8 x 128 = 1024
    kan_fused<<<grid, THREADS>>>(inp, gridp, coefp, sbase, ssp, maskp, out, batch);
}

// round 7
// speedup vs baseline: 2.2201x; 2.2201x over previous
#include <cuda_runtime.h>

// KAN layer as dense GEMM. Only 4 cubic-B-spline basis funcs are nonzero at
// any x, so per (b,i) we scatter them into a dense 9-vector F (8 basis slots
// + silu). Then out[b,o] = sum_k F[b,k] * C2[o,k], K = 64*9 = 576 — a plain
// fp32 GEMM with no data-dependent indexing in the hot loop.
//
//   kan_feat : Ft[k][b] (k = i*9+j), both read and write coalesced-ish
//   kan_c2t  : C2t[k][o] = mask*scale_sp*coef (j<8) / mask*scale_base (j=8)
//   kan_gemm : M=2048,N=64,K=576; split-K x9; 32b x 64o block tile, 128 thr,
//              4b x 4o register tile; per k: 2 LDS.128 (broadcast/cfree) + 16 FMA
//   kan_red  : deterministic fixed-order sum of 9 partials

#define IN_DIM  64
#define OUT_DIM 64
#define KDIM    (IN_DIM * 9)      // 576
#define MAXB    2048
#define KSPLIT  9
#define KCHUNK  (KDIM / KSPLIT)   // 64
#define MTILE   32

__device__ __align__(16) float g_Ft[KDIM * MAXB];            // 4.5 MB  [k][b]
__device__ __align__(16) float g_C2t[KDIM * OUT_DIM];        // 144 KB  [k][o]
__device__ __align__(16) float g_Part[KSPLIT * MAXB * OUT_DIM]; // 4.5 MB

// ---------------- phase 1: per-(b,i) dense feature vector -------------------
__global__ __launch_bounds__(256)
void kan_feat(const float* __restrict__ inp,
              const float* __restrict__ gridp,
              int batch)
{
    const int tid = blockIdx.x * blockDim.x + threadIdx.x;  // = i*MAXB + b
    const int b = tid & (MAXB - 1);
    const int i = tid >> 11;
    if (i >= IN_DIM) return;

    const float x = (b < batch) ? inp[b * IN_DIM + i] : 0.0f;

    const float g0 = __ldg(gridp + i * 6 + 0);
    const float g5 = __ldg(gridp + i * 6 + 5);
    const float h  = (g5 - g0) * 0.2f;
    const float t0 = g0 - 3.0f * h;
    const float mf = (x - t0) * (1.0f / h);

    int mi = (int)floorf(mf);
    const float ok = (mi >= 0 && mi < 11) ? 1.0f : 0.0f;
    mi = max(0, min(10, mi));

    const float u  = mf - (float)mi;
    const float v  = 1.0f - u;
    const float u2 = u * u;
    const float u3 = u2 * u;
    float w[4];
    w[0] = ok * (v * v * v * (1.0f / 6.0f));
    w[3] = ok * (u3 * (1.0f / 6.0f));
    w[1] = ok * ((2.0f / 3.0f) - u2 + 0.5f * u3);
    w[2] = ok - w[0] - w[1] - w[3];

    float f[9];
    #pragma unroll
    for (int j = 0; j < 9; ++j) f[j] = 0.0f;
    #pragma unroll
    for (int r = 0; r < 4; ++r) {
        const int j = mi - 3 + r;
        if (j >= 0 && j < 8) f[j] = w[r];
    }
    f[8] = __fdividef(x, 1.0f + __expf(-x));   // silu

    #pragma unroll
    for (int j = 0; j < 9; ++j)
        g_Ft[(i * 9 + j) * MAXB + b] = f[j];   // coalesced over b
}

// ---------------- phase 1b: scaled coefficient matrix -----------------------
__global__ __launch_bounds__(256)
void kan_c2t(const float* __restrict__ coefp,
             const float* __restrict__ sbase,
             const float* __restrict__ ssp,
             const float* __restrict__ maskp)
{
    const int tid = blockIdx.x * blockDim.x + threadIdx.x;  // = k*64 + o
    if (tid >= KDIM * OUT_DIM) return;
    const int o = tid & (OUT_DIM - 1);
    const int k = tid >> 6;
    const int i = k / 9;
    const int j = k - i * 9;
    const int s = o * IN_DIM + i;
    const float m = maskp[s];
    g_C2t[tid] = (j < 8) ? m * ssp[s] * __ldg(coefp + s * 8 + j)
                         : m * sbase[s];
}

// ---------------- phase 2: split-K GEMM -------------------------------------
__global__ __launch_bounds__(128)
void kan_gemm()
{
    __shared__ __align__(16) float As[32][36];   // [k][b], pad 4
    __shared__ __align__(16) float Bs[32][64];   // [k][o]

    const int mt = blockIdx.x;        // m-tile
    const int ks = blockIdx.y;        // k-split
    const int b0 = mt * MTILE;
    const int k0 = ks * KCHUNK;

    const int tid = threadIdx.x;
    const int tx = tid & 15;          // o-quad
    const int ty = tid >> 4;          // b-quad (0..7)

    float acc[4][4];
    #pragma unroll
    for (int a = 0; a < 4; ++a)
        #pragma unroll
        for (int c = 0; c < 4; ++c) acc[a][c] = 0.0f;

    #pragma unroll 1
    for (int kk = 0; kk < KCHUNK / 32; ++kk) {
        const int kb = k0 + kk * 32;

        // fill A: 32k x 32b = 256 float4, 2 per thread
        #pragma unroll
        for (int p = 0; p < 2; ++p) {
            const int q  = tid + 128 * p;
            const int ka = q >> 3;
            const int bq = (q & 7) * 4;
            *(float4*)&As[ka][bq] =
                *(const float4*)&g_Ft[(kb + ka) * MAXB + b0 + bq];
        }
        // fill B: 32k x 64o = 512 float4/4 -> 4 per thread
        #pragma unroll
        for (int p = 0; p < 4; ++p) {
            const int q   = tid + 128 * p;
            const int kr  = q >> 4;
            const int oq  = (q & 15) * 4;
            *(float4*)&Bs[kr][oq] =
                *(const float4*)&g_C2t[(kb + kr) * OUT_DIM + oq];
        }
        __syncthreads();

        #pragma unroll
        for (int k = 0; k < 32; ++k) {
            const float4 a = *(const float4*)&As[k][ty * 4];
            const float4 bq = *(const float4*)&Bs[k][tx * 4];
            acc[0][0] = fmaf(a.x, bq.x, acc[0][0]);
            acc[0][1] = fmaf(a.x, bq.y, acc[0][1]);
            acc[0][2] = fmaf(a.x, bq.z, acc[0][2]);
            acc[0][3] = fmaf(a.x, bq.w, acc[0][3]);
            acc[1][0] = fmaf(a.y, bq.x, acc[1][0]);
            acc[1][1] = fmaf(a.y, bq.y, acc[1][1]);
            acc[1][2] = fmaf(a.y, bq.z, acc[1][2]);
            acc[1][3] = fmaf(a.y, bq.w, acc[1][3]);
            acc[2][0] = fmaf(a.z, bq.x, acc[2][0]);
            acc[2][1] = fmaf(a.z, bq.y, acc[2][1]);
            acc[2][2] = fmaf(a.z, bq.z, acc[2][2]);
            acc[2][3] = fmaf(a.z, bq.w, acc[2][3]);
            acc[3][0] = fmaf(a.w, bq.x, acc[3][0]);
            acc[3][1] = fmaf(a.w, bq.y, acc[3][1]);
            acc[3][2] = fmaf(a.w, bq.z, acc[3][2]);
            acc[3][3] = fmaf(a.w, bq.w, acc[3][3]);
        }
        __syncthreads();
    }

    #pragma unroll
    for (int ib = 0; ib < 4; ++ib) {
        const int b = b0 + ty * 4 + ib;
        float4 vOut = make_float4(acc[ib][0], acc[ib][1], acc[ib][2], acc[ib][3]);
        *(float4*)&g_Part[((ks << 11) + b) * OUT_DIM + tx * 4] = vOut;
    }
}

// ---------------- phase 3: deterministic reduce -----------------------------
__global__ __launch_bounds__(256)
void kan_red(float* __restrict__ out, int batch)
{
    const int tid = blockIdx.x * blockDim.x + threadIdx.x;  // = b*16 + o4
    const int b  = tid >> 4;
    const int o4 = (tid & 15) * 4;
    if (b >= batch) return;

    float4 v = make_float4(0.f, 0.f, 0.f, 0.f);
    #pragma unroll
    for (int ks = 0; ks < KSPLIT; ++ks) {
        const float4 p = *(const float4*)&g_Part[((ks << 11) + b) * OUT_DIM + o4];
        v.x += p.x; v.y += p.y; v.z += p.z; v.w += p.w;
    }
    *(float4*)&out[b * OUT_DIM + o4] = v;
}

extern "C" void kernel_launch(void* const* d_in, const int* in_sizes, int n_in,
                              void* d_out, int out_size)
{
    const float* inp   = (const float*)d_in[0];   // (batch, 64)
    const float* gridp = (const float*)d_in[1];   // (4096, 6)
    const float* coefp = (const float*)d_in[2];   // (4096, 8)
    const float* sbase = (const float*)d_in[3];   // (4096,)
    const float* ssp   = (const float*)d_in[4];   // (4096,)
    const float* maskp = (const float*)d_in[5];   // (4096,)
    float* out = (float*)d_out;                   // (batch, 64)

    int batch = in_sizes[0] / IN_DIM;
    if (batch > MAXB) batch = MAXB;

    kan_feat<<<(IN_DIM * MAXB) / 256, 256>>>(inp, gridp, batch);
    kan_c2t<<<(KDIM * OUT_DIM + 255) / 256, 256>>>(coefp, sbase, ssp, maskp);

    const int mtiles = (batch + MTILE - 1) / MTILE;   // 64 @ batch=2048
    dim3 ggrid(mtiles, KSPLIT);                       // 64 x 9 = 576 blocks
    kan_gemm<<<ggrid, 128>>>();

    kan_red<<<(batch * 16 + 255) / 256, 256>>>(out, batch);
}